// round 3
// baseline (speedup 1.0000x reference)
#include <cuda_runtime.h>
#include <math.h>
#include <float.h>

#define Bn 32
#define Cc 32
#define HW 1024
#define Vv 4096
#define NPIX (Bn*Cc*HW)   // 1048576

// ---- static device scratch (no allocations allowed) ----
__device__ float g_frest[NPIX];     // 4 MB
__device__ float g_r[NPIX];         // 4 MB (downsampled vectors, layout [(b*C+c)*pnpn + p])
__device__ float g_h32[NPIX];       // 4 MB (reconstructed h at 32x32)
__device__ int   g_idx[Bn*HW];      // argmin indices, max N=32768
__device__ float g_hits[Vv];
__device__ float g_esq[Vv];
__device__ float g_M[5][32][16];    // bicubic matrices for pn=1,2,4,8,16
__device__ float g_part[256];
__device__ float g_pd[16384];       // partial argmin dists (V-split mode)
__device__ int   g_pv[16384];

// ---------------- init / copy ----------------
__global__ void k_copy(const float4* __restrict__ f) {
    int n4 = NPIX / 4;
    for (int i = blockIdx.x*blockDim.x + threadIdx.x; i < n4; i += gridDim.x*blockDim.x)
        ((float4*)g_frest)[i] = f[i];
}

__global__ void k_fill(float* __restrict__ out, int nz) {
    for (int i = blockIdx.x*blockDim.x + threadIdx.x; i < nz; i += gridDim.x*blockDim.x)
        out[i] = 0.f;
}

__global__ void k_setup(const float* __restrict__ emb) {
    int v = blockIdx.x*256 + threadIdx.x;
    if (v < Vv) {
        g_hits[v] = 0.f;
        const float* e = emb + v*32;
        float s = 0.f;
        #pragma unroll
        for (int c = 0; c < 32; c++) s += e[c]*e[c];
        g_esq[v] = s;
    }
    if (v < 160) {
        int si = v >> 5, i = v & 31;
        const int pns[5] = {1,2,4,8,16};
        int pn = pns[si];
        for (int j = 0; j < 16; j++) g_M[si][i][j] = 0.f;
        double scale = (double)pn / 32.0;
        double x = (i + 0.5)*scale - 0.5;
        double x0 = floor(x);
        double tt = x - x0;
        int ix0 = (int)x0;
        const double a = -0.75;
        for (int j = -1; j <= 2; j++) {
            double d = fabs(tt - (double)j);
            double w;
            if (d < 1.0)      w = (a+2.0)*d*d*d - (a+3.0)*d*d + 1.0;
            else if (d < 2.0) w = a*d*d*d - 5.0*a*d*d + 8.0*a*d - 4.0*a;
            else              w = 0.0;
            int col = ix0 + j;
            col = col < 0 ? 0 : (col > pn-1 ? pn-1 : col);
            g_M[si][i][col] = (float)((double)g_M[si][i][col] + w);
        }
    }
}

// ---------------- loss reduction (f_hat == 0, so loss = 7.5*mean(f^2)) ----------------
__global__ void k_rsum(const float* __restrict__ f) {
    __shared__ float red[256];
    int b = blockIdx.x, t = threadIdx.x;
    float s = 0.f;
    int base = b * 4096;
    for (int i = t; i < 4096; i += 256) { float v = f[base + i]; s = fmaf(v, v, s); }
    red[t] = s; __syncthreads();
    for (int o = 128; o > 0; o >>= 1) { if (t < o) red[t] += red[t+o]; __syncthreads(); }
    if (t == 0) g_part[b] = red[0];
}

// ---------------- area downsample ----------------
__global__ void k_down(int pn) {
    int pnpn = pn * pn;
    int s = 32 / pn;
    float inv = 1.f / (float)(s * s);
    int tot = Bn * Cc * pnpn;
    for (int i = blockIdx.x*blockDim.x + threadIdx.x; i < tot; i += gridDim.x*blockDim.x) {
        int bc = i / pnpn, p = i % pnpn;
        int ph = p / pn, pw = p % pn;
        const float* base = g_frest + bc*HW + (ph*s)*32 + pw*s;
        float acc = 0.f;
        for (int dy = 0; dy < s; dy++)
            for (int dx = 0; dx < s; dx++)
                acc += base[dy*32 + dx];
        g_r[i] = acc * inv;
    }
}

// ---------------- nearest-code argmin ----------------
// Block: 32 rows (one per lane), 8 warps split codes strided. V optionally split
// across blockIdx.y chunks (for small-N scales) with a separate reduce pass.
__global__ void __launch_bounds__(256) k_argmin(const float* __restrict__ emb,
                                                int N, int pnpn, int chunk,
                                                int useFrest, int TC) {
    extern __shared__ float sm[];            // TC*32 (codes) + TC (esq)
    float4* es4 = (float4*)sm;
    float* esq_s = sm + (size_t)TC * 32;
    __shared__ float sd[8*32];
    __shared__ int   sv[8*32];

    int t = threadIdx.x, w = t >> 5, l = t & 31;
    int n = blockIdx.x * 32 + l;
    const float* r = useFrest ? g_frest : g_r;
    int b = n / pnpn, p = n % pnpn;
    const float* zp = r + (size_t)b * 32 * pnpn + p;
    float z[32]; float zz = 0.f;
    #pragma unroll
    for (int c = 0; c < 32; c++) { z[c] = zp[(size_t)c * pnpn]; zz = fmaf(z[c], z[c], zz); }

    int v0 = blockIdx.y * chunk;
    float best = FLT_MAX; int bv = 0;
    for (int t0 = v0; t0 < v0 + chunk; t0 += TC) {
        __syncthreads();
        const float4* eg = (const float4*)(emb + (size_t)t0 * 32);
        for (int i = t; i < TC*8; i += 256) es4[i] = eg[i];
        for (int i = t; i < TC;   i += 256) esq_s[i] = g_esq[t0 + i];
        __syncthreads();
        for (int v = w; v < TC; v += 8) {
            const float4* ev = es4 + v*8;
            float4 e0 = ev[0], e1 = ev[1], e2 = ev[2], e3 = ev[3];
            float4 e4 = ev[4], e5 = ev[5], e6 = ev[6], e7 = ev[7];
            float a0 = z[0]*e0.x;  a0=fmaf(z[1],e0.y,a0);  a0=fmaf(z[2],e0.z,a0);  a0=fmaf(z[3],e0.w,a0);
            a0=fmaf(z[16],e4.x,a0); a0=fmaf(z[17],e4.y,a0); a0=fmaf(z[18],e4.z,a0); a0=fmaf(z[19],e4.w,a0);
            float a1 = z[4]*e1.x;  a1=fmaf(z[5],e1.y,a1);  a1=fmaf(z[6],e1.z,a1);  a1=fmaf(z[7],e1.w,a1);
            a1=fmaf(z[20],e5.x,a1); a1=fmaf(z[21],e5.y,a1); a1=fmaf(z[22],e5.z,a1); a1=fmaf(z[23],e5.w,a1);
            float a2 = z[8]*e2.x;  a2=fmaf(z[9],e2.y,a2);  a2=fmaf(z[10],e2.z,a2); a2=fmaf(z[11],e2.w,a2);
            a2=fmaf(z[24],e6.x,a2); a2=fmaf(z[25],e6.y,a2); a2=fmaf(z[26],e6.z,a2); a2=fmaf(z[27],e6.w,a2);
            float a3 = z[12]*e3.x; a3=fmaf(z[13],e3.y,a3); a3=fmaf(z[14],e3.z,a3); a3=fmaf(z[15],e3.w,a3);
            a3=fmaf(z[28],e7.x,a3); a3=fmaf(z[29],e7.y,a3); a3=fmaf(z[30],e7.z,a3); a3=fmaf(z[31],e7.w,a3);
            float dot = (a0 + a1) + (a2 + a3);
            float dist = (zz + esq_s[v]) - 2.f * dot;
            if (dist < best) { best = dist; bv = t0 + v; }
        }
    }
    sd[w*32 + l] = best; sv[w*32 + l] = bv;
    __syncthreads();
    if (w == 0) {
        float bb = sd[l]; int vv = sv[l];
        #pragma unroll
        for (int k = 1; k < 8; k++) {
            float d2 = sd[k*32 + l]; int v2 = sv[k*32 + l];
            if (d2 < bb || (d2 == bb && v2 < vv)) { bb = d2; vv = v2; }
        }
        if (gridDim.y == 1) {
            g_idx[n] = vv;
            atomicAdd(&g_hits[vv], 1.f);
        } else {
            g_pd[blockIdx.y * N + n] = bb;
            g_pv[blockIdx.y * N + n] = vv;
        }
    }
}

__global__ void k_red(int N, int VS) {
    for (int n = blockIdx.x*blockDim.x + threadIdx.x; n < N; n += gridDim.x*blockDim.x) {
        float bb = g_pd[n]; int vv = g_pv[n];
        for (int k = 1; k < VS; k++) {
            float d = g_pd[k*N + n];
            if (d < bb) { bb = d; vv = g_pv[k*N + n]; }
        }
        g_idx[n] = vv;
        atomicAdd(&g_hits[vv], 1.f);
    }
}

// ---------------- gather + separable bicubic upsample ----------------
__global__ void __launch_bounds__(256) k_ups(const float* __restrict__ emb, int pn, int sidx) {
    extern __shared__ float sm[];
    int pnpn = pn * pn;
    float* hq  = sm;                    // 32*pnpn
    float* tmp = hq + 32*pnpn;          // 32*pn*32
    float* Ms  = tmp + 32*pn*32;        // 32*pn
    int b = blockIdx.x, t = threadIdx.x;
    for (int i = t; i < 32*pn; i += 256) Ms[i] = g_M[sidx][i/pn][i%pn];
    for (int j = t; j < 32*pnpn; j += 256) {
        int c = j / pnpn, p = j % pnpn;
        hq[j] = emb[(size_t)g_idx[b*pnpn + p] * 32 + c];
    }
    __syncthreads();
    for (int j = t; j < 32*pn*32; j += 256) {
        int c = j / (pn*32); int rem = j % (pn*32); int h = rem >> 5; int X = rem & 31;
        float s = 0.f;
        for (int wv = 0; wv < pn; wv++) s = fmaf(Ms[X*pn + wv], hq[c*pnpn + h*pn + wv], s);
        tmp[j] = s;
    }
    __syncthreads();
    for (int j = t; j < 32768; j += 256) {
        int c = j >> 10, Y = (j >> 5) & 31, X = j & 31;
        float s = 0.f;
        for (int hv = 0; hv < pn; hv++) s = fmaf(Ms[Y*pn + hv], tmp[(c*pn + hv)*32 + X], s);
        g_h32[((b*32 + c) << 10) + (Y << 5) + X] = s;
    }
}

// ---------------- Phi (3x3 conv residual) + f_rest update ----------------
// grid (B, 8): block handles image b, 4 output channels. Full padded input in smem.
__global__ void __launch_bounds__(256) k_phi(const float* __restrict__ wgt,
                                             const float* __restrict__ bias) {
    extern __shared__ float sm[];
    float* in_s = sm;                   // 32*34*34 = 36992
    float* w_s  = sm + 36992;           // 4*32*9 = 1152
    float* b_s  = w_s + 1152;           // 4
    int b = blockIdx.x, cog = blockIdx.y, t = threadIdx.x;
    for (int i = t; i < 36992; i += 256) in_s[i] = 0.f;
    __syncthreads();
    const float* hb = g_h32 + (size_t)b * 32 * 1024;
    for (int i = t; i < 32768; i += 256) {
        int ci = i >> 10, y = (i >> 5) & 31, x = i & 31;
        in_s[ci*1156 + (y+1)*34 + (x+1)] = hb[i];
    }
    for (int i = t; i < 1152; i += 256) w_s[i] = wgt[cog*1152 + i];
    if (t < 4) b_s[t] = bias[cog*4 + t];
    __syncthreads();

    float acc[4][4];
    #pragma unroll
    for (int k = 0; k < 4; k++)
        #pragma unroll
        for (int q = 0; q < 4; q++) acc[k][q] = b_s[k];

    for (int ci = 0; ci < 32; ci++) {
        float wr[4][9];
        #pragma unroll
        for (int k = 0; k < 4; k++)
            #pragma unroll
            for (int j = 0; j < 9; j++) wr[k][j] = w_s[(k*32 + ci)*9 + j];
        #pragma unroll
        for (int q = 0; q < 4; q++) {
            int p = t + q*256;
            int y = p >> 5, x = p & 31;
            const float* ip = in_s + ci*1156 + y*34 + x;   // padded: (y+1-1, x+1-1)
            float v0 = ip[0],  v1 = ip[1],  v2 = ip[2];
            float v3 = ip[34], v4 = ip[35], v5 = ip[36];
            float v6 = ip[68], v7 = ip[69], v8 = ip[70];
            #pragma unroll
            for (int k = 0; k < 4; k++) {
                float a = acc[k][q];
                a = fmaf(v0, wr[k][0], a); a = fmaf(v1, wr[k][1], a); a = fmaf(v2, wr[k][2], a);
                a = fmaf(v3, wr[k][3], a); a = fmaf(v4, wr[k][4], a); a = fmaf(v5, wr[k][5], a);
                a = fmaf(v6, wr[k][6], a); a = fmaf(v7, wr[k][7], a); a = fmaf(v8, wr[k][8], a);
                acc[k][q] = a;
            }
        }
    }
    #pragma unroll
    for (int q = 0; q < 4; q++) {
        int p = t + q*256; int y = p >> 5, x = p & 31;
        #pragma unroll
        for (int k = 0; k < 4; k++) {
            int co = cog*4 + k;
            float hval = in_s[co*1156 + (y+1)*34 + (x+1)];
            float outv = 0.5f*hval + 0.5f*acc[k][q];
            g_frest[((b*32 + co) << 10) + p] -= outv;
        }
    }
}

// ---------------- finalize: loss + perplexity ----------------
__global__ void k_final(float* __restrict__ out, int osz) {
    __shared__ float red[256];
    int t = threadIdx.x;
    // sum of f^2 partials
    red[t] = g_part[t]; __syncthreads();
    for (int o = 128; o > 0; o >>= 1) { if (t < o) red[t] += red[t+o]; __syncthreads(); }
    float S = red[0]; __syncthreads();
    float m = S / (float)NPIX;
    // total hits
    float h = 0.f;
    for (int k = 0; k < 16; k++) h += g_hits[t + k*256];
    red[t] = h; __syncthreads();
    for (int o = 128; o > 0; o >>= 1) { if (t < o) red[t] += red[t+o]; __syncthreads(); }
    float tot = red[0]; __syncthreads();
    float denom = fmaxf(tot, 1.f);
    // entropy
    float e = 0.f;
    for (int k = 0; k < 16; k++) {
        float p = g_hits[t + k*256] / denom;
        e += p * logf(p + 1e-10f);
    }
    red[t] = e; __syncthreads();
    for (int o = 128; o > 0; o >>= 1) { if (t < o) red[t] += red[t+o]; __syncthreads(); }
    if (t == 0) {
        float ent = red[0];
        float loss = 0.f;
        for (int si = 0; si < 6; si++) { loss = loss + 0.25f*m; loss = loss + m; }
        out[osz - 2] = loss;
        out[osz - 1] = expf(-ent);
    }
}

// ---------------- launcher ----------------
extern "C" void kernel_launch(void* const* d_in, const int* in_sizes, int n_in,
                              void* d_out, int out_size) {
    const float* f   = (const float*)d_in[0];
    const float* emb = (const float*)d_in[1];
    const float* pw  = (const float*)d_in[2];
    const float* pb  = (const float*)d_in[3];
    float* out = (float*)d_out;

    const int phiSel[6] = {0,0,1,2,3,3};
    const int pns[6]    = {1,2,4,8,16,32};
    const int VSs[6]    = {16,16,8,4,1,1};

    cudaFuncSetAttribute(k_argmin, cudaFuncAttributeMaxDynamicSharedMemorySize, 70*1024);
    cudaFuncSetAttribute(k_ups,    cudaFuncAttributeMaxDynamicSharedMemorySize, 102*1024);
    cudaFuncSetAttribute(k_phi,    cudaFuncAttributeMaxDynamicSharedMemorySize, 156*1024);

    k_copy<<<512, 256>>>((const float4*)f);
    k_fill<<<512, 256>>>(out, out_size - 2);
    k_setup<<<16, 256>>>(emb);
    k_rsum<<<256, 256>>>(f);

    for (int si = 0; si < 6; si++) {
        int pn = pns[si], pnpn = pn*pn, N = 32*pnpn;
        if (si < 5) {
            int tot = 32*32*pnpn;
            int blocks = (tot + 255) / 256; if (blocks > 512) blocks = 512;
            k_down<<<blocks, 256>>>(pn);
        }
        int VS = VSs[si], chunk = 4096 / VS;
        int TC = chunk < 512 ? chunk : 512;
        size_t smem = (size_t)TC * 33 * sizeof(float);
        k_argmin<<<dim3(N/32, VS), 256, smem>>>(emb, N, pnpn, chunk, si == 5 ? 1 : 0, TC);
        if (VS > 1) k_red<<<(N + 255)/256, 256>>>(N, VS);
        if (si < 5) {
            size_t us = (size_t)(32*pnpn + 32*pn*32 + 32*pn) * sizeof(float);
            k_ups<<<32, 256, us>>>(emb, pn, si);
            size_t ps = (size_t)(36992 + 1152 + 4) * sizeof(float);
            k_phi<<<dim3(32, 8), 256, ps>>>(pw + phiSel[si]*32*32*9, pb + phiSel[si]*32);
        }
    }
    k_final<<<1, 256>>>(out, out_size);
}

// round 5
// speedup vs baseline: 1.1823x; 1.1823x over previous
#include <cuda_runtime.h>
#include <math.h>
#include <float.h>

#define Bn 32
#define Cc 32
#define HW 1024
#define Vv 4096
#define NPIX (Bn*Cc*HW)   // 1048576

typedef unsigned long long ull;

// ---- static device scratch (no allocations allowed) ----
__device__ float g_frest[NPIX];     // 4 MB
__device__ float g_r[NPIX];         // 4 MB (downsampled vectors)
__device__ float g_h32[NPIX];       // 4 MB (reconstructed h at 32x32)
__device__ int   g_idx[Bn*HW];
__device__ float g_hits[Vv];
__device__ float g_esq[Vv];
__device__ float g_M[5][32][16];    // bicubic matrices for pn=1,2,4,8,16
__device__ float g_part[512];
__device__ float g_pd[16384];       // partial argmin dists (V-split mode)
__device__ int   g_pv[16384];

// ---- packed f32x2 helpers (FFMA2 — PTX-only on sm_103a) ----
__device__ __forceinline__ ull pack2(float lo, float hi) {
    ull d;
    asm("mov.b64 %0, {%1, %2};" : "=l"(d)
        : "r"(__float_as_uint(lo)), "r"(__float_as_uint(hi)));
    return d;
}
__device__ __forceinline__ float2 unpack2(ull v) {
    unsigned int lo, hi;
    asm("mov.b64 {%0, %1}, %2;" : "=r"(lo), "=r"(hi) : "l"(v));
    return make_float2(__uint_as_float(lo), __uint_as_float(hi));
}
__device__ __forceinline__ ull fma2(ull a, ull b, ull c) {
    ull d;
    asm("fma.rn.f32x2 %0, %1, %2, %3;" : "=l"(d) : "l"(a), "l"(b), "l"(c));
    return d;
}
__device__ __forceinline__ ull add2(ull a, ull b) {
    ull d;
    asm("add.rn.f32x2 %0, %1, %2;" : "=l"(d) : "l"(a), "l"(b));
    return d;
}

// ---------------- fused: copy f -> g_frest, zero d_out, sum f^2 ----------------
__global__ void k_prep(const float4* __restrict__ f, float4* __restrict__ out4) {
    __shared__ float red[256];
    int t = threadIdx.x;
    float s = 0.f;
    const int n4 = NPIX / 4;
    for (int i = blockIdx.x*256 + t; i < n4; i += gridDim.x*256) {
        float4 v = f[i];
        ((float4*)g_frest)[i] = v;
        s = fmaf(v.x, v.x, fmaf(v.y, v.y, fmaf(v.z, v.z, fmaf(v.w, v.w, s))));
        out4[i] = make_float4(0.f, 0.f, 0.f, 0.f);
    }
    red[t] = s; __syncthreads();
    for (int o = 128; o > 0; o >>= 1) { if (t < o) red[t] += red[t+o]; __syncthreads(); }
    if (t == 0) g_part[blockIdx.x] = red[0];
}

__global__ void k_setup(const float* __restrict__ emb) {
    int v = blockIdx.x*256 + threadIdx.x;
    if (v < Vv) {
        g_hits[v] = 0.f;
        const float* e = emb + v*32;
        float s = 0.f;
        #pragma unroll
        for (int c = 0; c < 32; c++) s += e[c]*e[c];
        g_esq[v] = s;
    }
    if (v < 160) {
        int si = v >> 5, i = v & 31;
        const int pns[5] = {1,2,4,8,16};
        int pn = pns[si];
        for (int j = 0; j < 16; j++) g_M[si][i][j] = 0.f;
        double scale = (double)pn / 32.0;
        double x = (i + 0.5)*scale - 0.5;
        double x0 = floor(x);
        double tt = x - x0;
        int ix0 = (int)x0;
        const double a = -0.75;
        for (int j = -1; j <= 2; j++) {
            double d = fabs(tt - (double)j);
            double w;
            if (d < 1.0)      w = (a+2.0)*d*d*d - (a+3.0)*d*d + 1.0;
            else if (d < 2.0) w = a*d*d*d - 5.0*a*d*d + 8.0*a*d - 4.0*a;
            else              w = 0.0;
            int col = ix0 + j;
            col = col < 0 ? 0 : (col > pn-1 ? pn-1 : col);
            g_M[si][i][col] = (float)((double)g_M[si][i][col] + w);
        }
    }
}

// ---------------- area downsample ----------------
__global__ void k_down(int pn) {
    int pnpn = pn * pn;
    int s = 32 / pn;
    float inv = 1.f / (float)(s * s);
    int tot = Bn * Cc * pnpn;
    for (int i = blockIdx.x*blockDim.x + threadIdx.x; i < tot; i += gridDim.x*blockDim.x) {
        int bc = i / pnpn, p = i % pnpn;
        int ph = p / pn, pw = p % pn;
        const float* base = g_frest + bc*HW + (ph*s)*32 + pw*s;
        float acc = 0.f;
        for (int dy = 0; dy < s; dy++)
            for (int dx = 0; dx < s; dx++)
                acc += base[dy*32 + dx];
        g_r[i] = acc * inv;
    }
}

// ---------------- nearest-code argmin (FFMA2 inner loop) ----------------
// dist ordering uses esq - 2*dot (zz dropped: constant per row, argmin-invariant).
__global__ void __launch_bounds__(256) k_argmin(const float* __restrict__ emb,
                                                int N, int pnpn, int chunk,
                                                int useFrest, int TC) {
    extern __shared__ float sm[];            // TC*32 (codes) + TC (esq)
    float4* es4 = (float4*)sm;
    float* esq_s = sm + (size_t)TC * 32;
    __shared__ float sd[256];
    __shared__ int   sv[256];

    int t = threadIdx.x, w = t >> 5, l = t & 31;
    int n = blockIdx.x * 32 + l;
    const float* r = useFrest ? g_frest : g_r;
    int b = n / pnpn, p = n % pnpn;
    const float* zsrc = r + (size_t)b * 32 * pnpn + p;
    ull zp[16];
    #pragma unroll
    for (int c = 0; c < 16; c++)
        zp[c] = pack2(zsrc[(size_t)(2*c) * pnpn], zsrc[(size_t)(2*c+1) * pnpn]);

    int v0 = blockIdx.y * chunk;
    float best = FLT_MAX; int bv = 0;
    for (int t0 = v0; t0 < v0 + chunk; t0 += TC) {
        __syncthreads();
        const float4* eg = (const float4*)(emb + (size_t)t0 * 32);
        for (int i = t; i < TC*8; i += 256) es4[i] = eg[i];
        for (int i = t; i < TC;   i += 256) esq_s[i] = g_esq[t0 + i];
        __syncthreads();
        for (int v = w; v < TC; v += 8) {
            const ulonglong2* evp = (const ulonglong2*)(es4 + v*8);
            ull a0 = 0ull, a1 = 0ull;
            #pragma unroll
            for (int i = 0; i < 8; i++) {
                ulonglong2 q = evp[i];
                a0 = fma2(zp[2*i],   q.x, a0);
                a1 = fma2(zp[2*i+1], q.y, a1);
            }
            float2 pq = unpack2(add2(a0, a1));
            float dot = pq.x + pq.y;
            float dist = fmaf(-2.f, dot, esq_s[v]);
            if (dist < best) { best = dist; bv = t0 + v; }
        }
    }
    sd[t] = best; sv[t] = bv;
    __syncthreads();
    if (w == 0) {
        float bb = sd[l]; int vv = sv[l];
        #pragma unroll
        for (int k = 1; k < 8; k++) {
            float d2 = sd[k*32 + l]; int v2 = sv[k*32 + l];
            if (d2 < bb || (d2 == bb && v2 < vv)) { bb = d2; vv = v2; }
        }
        if (gridDim.y == 1) {
            g_idx[n] = vv;
            atomicAdd(&g_hits[vv], 1.f);
        } else {
            g_pd[blockIdx.y * N + n] = bb;
            g_pv[blockIdx.y * N + n] = vv;
        }
    }
}

__global__ void k_red(int N, int VS) {
    for (int n = blockIdx.x*blockDim.x + threadIdx.x; n < N; n += gridDim.x*blockDim.x) {
        float bb = g_pd[n]; int vv = g_pv[n];
        for (int k = 1; k < VS; k++) {
            float d = g_pd[k*N + n];
            if (d < bb) { bb = d; vv = g_pv[k*N + n]; }
        }
        g_idx[n] = vv;
        atomicAdd(&g_hits[vv], 1.f);
    }
}

// ---------------- gather + separable bicubic upsample (grid: B x 8 ch-groups) ----------------
__global__ void __launch_bounds__(256) k_ups(const float* __restrict__ emb, int pn, int sidx) {
    extern __shared__ float sm[];
    int pnpn = pn * pn;
    float* hq  = sm;                    // 4*pnpn
    float* tmp = hq + 4*pnpn;           // 4*pn*32
    float* Ms  = tmp + 4*pn*32;         // 32*pn
    int b = blockIdx.x, cg = blockIdx.y, t = threadIdx.x;
    for (int i = t; i < 32*pn; i += 256) Ms[i] = g_M[sidx][i/pn][i%pn];
    for (int j = t; j < 4*pnpn; j += 256) {
        int c = j / pnpn, p = j % pnpn;
        hq[j] = emb[(size_t)g_idx[b*pnpn + p] * 32 + cg*4 + c];
    }
    __syncthreads();
    for (int j = t; j < 4*pn*32; j += 256) {
        int c = j / (pn*32); int rem = j % (pn*32); int h = rem >> 5; int X = rem & 31;
        float s = 0.f;
        for (int wv = 0; wv < pn; wv++) s = fmaf(Ms[X*pn + wv], hq[c*pnpn + h*pn + wv], s);
        tmp[j] = s;
    }
    __syncthreads();
    for (int j = t; j < 4096; j += 256) {
        int c = j >> 10, Y = (j >> 5) & 31, X = j & 31;
        float s = 0.f;
        for (int hv = 0; hv < pn; hv++) s = fmaf(Ms[Y*pn + hv], tmp[(c*pn + hv)*32 + X], s);
        g_h32[((b*32 + cg*4 + c) << 10) + (Y << 5) + X] = s;
    }
}

// ---------------- Phi (3x3 conv residual, FFMA2) + f_rest update ----------------
// grid (B, 8): image b, 4 output channels. Padded input (34 rows x 36-col stride) in smem.
#define PHI_CI 1224   // 34*36
__global__ void __launch_bounds__(256) k_phi(const float* __restrict__ wgt,
                                             const float* __restrict__ bias) {
    extern __shared__ float sm[];
    float* in_s = sm;                    // 32*1224 = 39168 floats
    ull*   w2   = (ull*)(sm + 39168);    // 1152 packed (w,w) pairs
    float* b_s  = sm + 39168 + 2304;     // 4
    int b = blockIdx.x, cog = blockIdx.y, t = threadIdx.x;
    for (int i = t; i < 32*PHI_CI; i += 256) in_s[i] = 0.f;
    __syncthreads();
    const float* hb = g_h32 + (size_t)b * 32768;
    for (int i = t; i < 32768; i += 256) {
        int ci = i >> 10, y = (i >> 5) & 31, x = i & 31;
        in_s[ci*PHI_CI + (y+1)*36 + (x+1)] = hb[i];
    }
    for (int i = t; i < 1152; i += 256) { float w = wgt[cog*1152 + i]; w2[i] = pack2(w, w); }
    if (t < 4) b_s[t] = bias[cog*4 + t];
    __syncthreads();

    int y = t >> 3, x0 = (t & 7) * 4;
    ull accA[4], accB[4];
    #pragma unroll
    for (int k = 0; k < 4; k++) { ull bb = pack2(b_s[k], b_s[k]); accA[k] = bb; accB[k] = bb; }

    for (int ci = 0; ci < 32; ci++) {
        ull pr[3][5];
        #pragma unroll
        for (int rr = 0; rr < 3; rr++) {
            const float* row = in_s + ci*PHI_CI + (y+rr)*36 + x0;  // 16B aligned
            float4 u03 = *(const float4*)row;
            float2 u45 = *(const float2*)(row + 4);
            pr[rr][0] = pack2(u03.x, u03.y);
            pr[rr][1] = pack2(u03.y, u03.z);
            pr[rr][2] = pack2(u03.z, u03.w);
            pr[rr][3] = pack2(u03.w, u45.x);
            pr[rr][4] = pack2(u45.x, u45.y);
        }
        #pragma unroll
        for (int k = 0; k < 4; k++) {
            const ull* wk = w2 + (k*32 + ci)*9;
            ull a = accA[k], c2 = accB[k];
            #pragma unroll
            for (int rr = 0; rr < 3; rr++) {
                ull w0 = wk[rr*3], w1 = wk[rr*3+1], wv2 = wk[rr*3+2];
                a  = fma2(pr[rr][0], w0, a);
                a  = fma2(pr[rr][1], w1, a);
                a  = fma2(pr[rr][2], wv2, a);
                c2 = fma2(pr[rr][2], w0, c2);
                c2 = fma2(pr[rr][3], w1, c2);
                c2 = fma2(pr[rr][4], wv2, c2);
            }
            accA[k] = a; accB[k] = c2;
        }
    }
    #pragma unroll
    for (int k = 0; k < 4; k++) {
        float2 pa = unpack2(accA[k]);
        float2 pb = unpack2(accB[k]);
        float conv[4] = {pa.x, pa.y, pb.x, pb.y};
        int co = cog*4 + k;
        #pragma unroll
        for (int q = 0; q < 4; q++) {
            int x = x0 + q;
            float hval = in_s[co*PHI_CI + (y+1)*36 + (x+1)];
            float outv = 0.5f*hval + 0.5f*conv[q];
            g_frest[((b*32 + co) << 10) + (y << 5) + x] -= outv;
        }
    }
}

// ---------------- finalize: loss + perplexity ----------------
__global__ void k_final(float* __restrict__ out, int osz) {
    __shared__ float red[256];
    int t = threadIdx.x;
    red[t] = g_part[t] + g_part[t + 256]; __syncthreads();
    for (int o = 128; o > 0; o >>= 1) { if (t < o) red[t] += red[t+o]; __syncthreads(); }
    float S = red[0]; __syncthreads();
    float m = S / (float)NPIX;
    float h = 0.f;
    for (int k = 0; k < 16; k++) h += g_hits[t + k*256];
    red[t] = h; __syncthreads();
    for (int o = 128; o > 0; o >>= 1) { if (t < o) red[t] += red[t+o]; __syncthreads(); }
    float tot = red[0]; __syncthreads();
    float denom = fmaxf(tot, 1.f);
    float e = 0.f;
    for (int k = 0; k < 16; k++) {
        float p = g_hits[t + k*256] / denom;
        e += p * logf(p + 1e-10f);
    }
    red[t] = e; __syncthreads();
    for (int o = 128; o > 0; o >>= 1) { if (t < o) red[t] += red[t+o]; __syncthreads(); }
    if (t == 0) {
        float ent = red[0];
        float loss = 0.f;
        for (int si = 0; si < 6; si++) { loss = loss + 0.25f*m; loss = loss + m; }
        out[osz - 2] = loss;
        out[osz - 1] = expf(-ent);
    }
}

// ---------------- launcher ----------------
extern "C" void kernel_launch(void* const* d_in, const int* in_sizes, int n_in,
                              void* d_out, int out_size) {
    const float* f   = (const float*)d_in[0];
    const float* emb = (const float*)d_in[1];
    const float* pw  = (const float*)d_in[2];
    const float* pb  = (const float*)d_in[3];
    float* out = (float*)d_out;

    const int phiSel[6] = {0,0,1,2,3,3};
    const int pns[6]    = {1,2,4,8,16,32};
    const int VSs[6]    = {32,16,8,4,2,1};

    cudaFuncSetAttribute(k_argmin, cudaFuncAttributeMaxDynamicSharedMemorySize, 70*1024);
    cudaFuncSetAttribute(k_phi,    cudaFuncAttributeMaxDynamicSharedMemorySize, 168*1024);

    k_prep<<<512, 256>>>((const float4*)f, (float4*)out);
    k_setup<<<16, 256>>>(emb);

    for (int si = 0; si < 6; si++) {
        int pn = pns[si], pnpn = pn*pn, N = 32*pnpn;
        if (si < 5) {
            int tot = 32*32*pnpn;
            int blocks = (tot + 255) / 256; if (blocks > 512) blocks = 512;
            k_down<<<blocks, 256>>>(pn);
        }
        int VS = VSs[si], chunk = 4096 / VS;
        int TC = chunk < 512 ? chunk : 512;
        size_t smem = (size_t)TC * 33 * sizeof(float);
        k_argmin<<<dim3(N/32, VS), 256, smem>>>(emb, N, pnpn, chunk, si == 5 ? 1 : 0, TC);
        if (VS > 1) k_red<<<(N + 255)/256, 256>>>(N, VS);
        if (si < 5) {
            size_t us = (size_t)(4*pnpn + 4*pn*32 + 32*pn) * sizeof(float);
            k_ups<<<dim3(32, 8), 256, us>>>(emb, pn, si);
            size_t ps = (size_t)(39168 + 2304 + 4) * sizeof(float);
            k_phi<<<dim3(32, 8), 256, ps>>>(pw + phiSel[si]*32*32*9, pb + phiSel[si]*32);
        }
    }
    k_final<<<1, 256>>>(out, out_size);
}